// round 7
// baseline (speedup 1.0000x reference)
#include <cuda_runtime.h>
#include <cuda_bf16.h>
#include <mma.h>
#include <cstdint>

using namespace nvcuda;

#define N_TOK   65536
#define K_IN    64
#define E_DIM   512
#define V_SIZE  2048
#define CAND_CAP 16

typedef unsigned long long ull;

// ---- scratch (device globals: no runtime allocation allowed) ----
__device__ float           g_zp [(size_t)N_TOK * E_DIM];   // pre-conv output fp32
__device__ __nv_bfloat16   g_zpH[(size_t)N_TOK * E_DIM];   // zp in bf16 (RN)
__device__ __nv_bfloat16   g_ebH[(size_t)V_SIZE * E_DIM];  // emb in bf16 (RN)
__device__ float           g_C  [N_TOK];                   // |zp|^2 per row
__device__ float           g_e2 [V_SIZE];                  // |emb|^2 per code
__device__ int             g_tok[N_TOK];                   // final tokens
__device__ float           g_P  [(size_t)V_SIZE * 64];     // emb @ post_W + post_b
__device__ int             g_cand [(size_t)N_TOK * CAND_CAP];
__device__ int             g_ncand[N_TOK];                 // -1 = overflow (full rescan)

// ---- packed fp32x2 helpers (exact IEEE fp32 per lane) ----
__device__ __forceinline__ ull fma2(ull a, ull b, ull c) {
    ull d; asm("fma.rn.f32x2 %0, %1, %2, %3;" : "=l"(d) : "l"(a), "l"(b), "l"(c)); return d;
}
__device__ __forceinline__ ull dup2(float x) {
    ull d; asm("mov.b64 %0, {%1, %1};" : "=l"(d) : "f"(x)); return d;
}
__device__ __forceinline__ ull pack2(float x, float y) {
    ull d; asm("mov.b64 %0, {%1, %2};" : "=l"(d) : "f"(x), "f"(y)); return d;
}
__device__ __forceinline__ float2 unpack2(ull v) {
    float2 r; asm("mov.b64 {%0, %1}, %2;" : "=f"(r.x), "=f"(r.y) : "l"(v)); return r;
}

// ============================================================
// Kernel 0: e2[v] = sum_k emb[v,k]^2, plus bf16 copy of emb
// ============================================================
__global__ void e2_kernel(const float* __restrict__ emb) {
    int v = blockIdx.x;
    const float* row = emb + (size_t)v * E_DIM;
    float s = 0.f;
    for (int k = threadIdx.x; k < E_DIM; k += 128) {
        float x = row[k];
        g_ebH[(size_t)v * E_DIM + k] = __float2bfloat16(x);
        s = fmaf(x, x, s);
    }
    for (int off = 16; off > 0; off >>= 1)
        s += __shfl_down_sync(0xffffffffu, s, off);
    __shared__ float ws[4];
    int lane = threadIdx.x & 31, warp = threadIdx.x >> 5;
    if (lane == 0) ws[warp] = s;
    __syncthreads();
    if (threadIdx.x == 0)
        g_e2[v] = ws[0] + ws[1] + ws[2] + ws[3];
}

// ============================================================
// Kernel 1: zp = z @ pre_W + pre_b (FFMA2), C = |zp|^2, bf16 copy
// ============================================================
__global__ __launch_bounds__(128) void pre_kernel(
    const float* __restrict__ z, const float* __restrict__ W,
    const float* __restrict__ b)
{
    int n = blockIdx.x;
    __shared__ float zs[K_IN];
    if (threadIdx.x < K_IN) zs[threadIdx.x] = z[(size_t)n * K_IN + threadIdx.x];
    __syncthreads();

    int j0 = threadIdx.x * 4;
    float4 b4 = *(const float4*)&b[j0];
    ull acc0 = pack2(b4.x, b4.y);
    ull acc1 = pack2(b4.z, b4.w);

    #pragma unroll 16
    for (int k = 0; k < K_IN; k++) {
        ull zk = dup2(zs[k]);
        float4 w = *(const float4*)&W[(size_t)k * E_DIM + j0];
        acc0 = fma2(zk, pack2(w.x, w.y), acc0);
        acc1 = fma2(zk, pack2(w.z, w.w), acc1);
    }

    float2 p0 = unpack2(acc0), p1 = unpack2(acc1);
    float4 r; r.x = p0.x; r.y = p0.y; r.z = p1.x; r.w = p1.y;
    *(float4*)&g_zp[(size_t)n * E_DIM + j0] = r;

    __nv_bfloat162 h0 = __floats2bfloat162_rn(r.x, r.y);
    __nv_bfloat162 h1 = __floats2bfloat162_rn(r.z, r.w);
    *(__nv_bfloat162*)&g_zpH[(size_t)n * E_DIM + j0]     = h0;
    *(__nv_bfloat162*)&g_zpH[(size_t)n * E_DIM + j0 + 2] = h1;

    float s = r.x * r.x;
    s = fmaf(r.y, r.y, s);
    s = fmaf(r.z, r.z, s);
    s = fmaf(r.w, r.w, s);
    for (int off = 16; off > 0; off >>= 1)
        s += __shfl_down_sync(0xffffffffu, s, off);
    __shared__ float ws[4];
    int lane = threadIdx.x & 31, warp = threadIdx.x >> 5;
    if (lane == 0) ws[warp] = s;
    __syncthreads();
    if (threadIdx.x == 0)
        g_C[n] = ws[0] + ws[1] + ws[2] + ws[3];
}

// ============================================================
// Kernel 2: WMMA bf16 filter (legacy HMMA, baseline PTX).
// Per CTA: 128 rows x all 2048 codes. A resident in smem
// (128x512 bf16, ldm 520); B streamed double-buffered in
// 128x32 chunks; D = dot~ in smem (128x132 f32).
// Per-vtile epilogue: d~ = fmaf(-2,dot~, C+e2); codes within
// thr of running min -> candidate list (superset of exact
// argmin set by the bf16 conversion bound).
// ============================================================
#define FM 128
#define FN 128
#define A_LDM 520
#define B_LDM 40
#define D_LDM 132
#define N_VT (V_SIZE / FN)       // 16
#define N_KC (E_DIM / 32)        // 16 k-chunks per vtile
#define N_CH (N_VT * N_KC)       // 256 chunks total

#define OFF_A  0
#define OFF_B  (FM * A_LDM * 2)                    // 133120
#define OFF_D  (OFF_B + 2 * FN * B_LDM * 2)        // 153600
#define OFF_E2 (OFF_D + FM * D_LDM * 4)            // 221184
#define FIL_SMEM (OFF_E2 + FN * 4)                 // 221696

__global__ __launch_bounds__(256, 1) void filter_kernel()
{
    extern __shared__ unsigned char smem[];
    __nv_bfloat16* sA = (__nv_bfloat16*)(smem + OFF_A);
    __nv_bfloat16* sB = (__nv_bfloat16*)(smem + OFF_B);   // 2 bufs [128][40]
    float*         sD = (float*)(smem + OFF_D);           // [128][132]
    float*        sE2 = (float*)(smem + OFF_E2);

    int tid = threadIdx.x;
    int w   = tid >> 5;
    int wm  = w & 3;          // warp row block (32 rows each)
    int wn  = w >> 2;         // warp col block (64 cols each)
    int m0  = blockIdx.x * FM;

    // ---- load A block once: 128 rows x 512 k (bf16) ----
    {
        int row8 = tid >> 3;          // reuse tid mapping: 8192 uint4 total
        #pragma unroll
        for (int i = 0; i < 32; i++) {
            int idx = tid + 256 * i;
            int row = idx >> 6, c16 = idx & 63;
            uint4 v = *(const uint4*)(g_zpH + (size_t)(m0 + row) * E_DIM + c16 * 8);
            *(uint4*)((unsigned char*)sA + row * (A_LDM * 2) + c16 * 16) = v;
        }
        (void)row8;
    }

    // ---- B chunk load/store helpers ----
    uint4 pB[2];
    #define LOADB(cc) do {                                                   \
        int _v  = (cc) >> 4, _kc = (cc) & 15;                                \
        _Pragma("unroll")                                                    \
        for (int _i = 0; _i < 2; _i++) {                                     \
            int _idx = tid + 256 * _i;                                       \
            int _row = _idx >> 2, _q = _idx & 3;                             \
            pB[_i] = *(const uint4*)(g_ebH +                                 \
                (size_t)(_v * FN + _row) * E_DIM + _kc * 32 + _q * 8);       \
        }                                                                    \
    } while (0)
    #define STSB(bf) do {                                                    \
        _Pragma("unroll")                                                    \
        for (int _i = 0; _i < 2; _i++) {                                     \
            int _idx = tid + 256 * _i;                                       \
            int _row = _idx >> 2, _q = _idx & 3;                             \
            *(uint4*)((unsigned char*)sB + (bf) * (FN * B_LDM * 2)           \
                      + _row * (B_LDM * 2) + _q * 16) = pB[_i];              \
        }                                                                    \
    } while (0)

    // ---- per-row candidate state (thread tid < 128 owns row m0+tid) ----
    float Ci = 0.f, thr = 0.f;
    if (tid < FM) {
        Ci  = g_C[m0 + tid];
        thr = sqrtf(Ci) * (0.01105f * 0.015625f) + 1e-4f;
    }
    float bd = 3.4e38f, bthr = 3.4e38f;
    float cdv[CAND_CAP];
    int   cvv[CAND_CAP];
    int   cnt = 0;
    bool  bad = false;

    // ---- fragments ----
    wmma::fragment<wmma::accumulator, 16, 16, 16, float> cf[2][4];

    LOADB(0);
    STSB(0);
    LOADB(1);
    __syncthreads();     // A + B buf0 visible

    #pragma unroll 1
    for (int c = 0; c < N_CH; c++) {
        int buf = c & 1;
        int kc  = c & 15;

        if (c + 1 < N_CH) {
            STSB(buf ^ 1);                        // regs hold chunk c+1
            int nx = (c + 2 < N_CH) ? c + 2 : N_CH - 1;
            LOADB(nx);
        }

        if (kc == 0) {
            #pragma unroll
            for (int i = 0; i < 2; i++)
                #pragma unroll
                for (int j = 0; j < 4; j++)
                    wmma::fill_fragment(cf[i][j], 0.0f);
        }

        // ---- MMA: 32 k-values from buf ----
        int ks0 = kc * 32;
        #pragma unroll
        for (int ks = 0; ks < 32; ks += 16) {
            wmma::fragment<wmma::matrix_a, 16, 16, 16, __nv_bfloat16, wmma::row_major> af[2];
            wmma::fragment<wmma::matrix_b, 16, 16, 16, __nv_bfloat16, wmma::col_major> bfr[4];
            #pragma unroll
            for (int i = 0; i < 2; i++)
                wmma::load_matrix_sync(af[i],
                    sA + (size_t)(wm * 32 + i * 16) * A_LDM + ks0 + ks, A_LDM);
            #pragma unroll
            for (int j = 0; j < 4; j++)
                wmma::load_matrix_sync(bfr[j],
                    sB + buf * (FN * B_LDM) + (size_t)(wn * 64 + j * 16) * B_LDM + ks, B_LDM);
            #pragma unroll
            for (int i = 0; i < 2; i++)
                #pragma unroll
                for (int j = 0; j < 4; j++)
                    wmma::mma_sync(cf[i][j], af[i], bfr[j], cf[i][j]);
        }

        __syncthreads();   // buf consumed; buf^1 stores complete

        if (kc == 15) {
            int vt = c >> 4;
            // store dot~ tile to smem D
            #pragma unroll
            for (int i = 0; i < 2; i++)
                #pragma unroll
                for (int j = 0; j < 4; j++)
                    wmma::store_matrix_sync(
                        sD + (size_t)(wm * 32 + i * 16) * D_LDM + wn * 64 + j * 16,
                        cf[i][j], D_LDM, wmma::mem_row_major);
            if (tid < FN) sE2[tid] = g_e2[vt * FN + tid];
            __syncthreads();

            if (tid < FM) {
                const float* drow = sD + (size_t)tid * D_LDM;
                #pragma unroll 1
                for (int cb = 0; cb < FN / 4; cb++) {
                    float4 d4 = *(const float4*)(drow + cb * 4);
                    float dv[4] = {d4.x, d4.y, d4.z, d4.w};
                    #pragma unroll
                    for (int q = 0; q < 4; q++) {
                        int vcode = vt * FN + cb * 4 + q;
                        float d = fmaf(-2.0f, dv[q], Ci + sE2[cb * 4 + q]);
                        if (d < bd) { bd = d; bthr = bd + thr; }
                        if (d <= bthr) {
                            if (cnt == CAND_CAP) {      // compact vs tighter bound
                                int jj = 0;
                                for (int i2 = 0; i2 < CAND_CAP; i2++)
                                    if (cdv[i2] <= bthr) { cdv[jj] = cdv[i2]; cvv[jj] = cvv[i2]; jj++; }
                                cnt = jj;
                            }
                            if (cnt == CAND_CAP) bad = true;
                            else { cdv[cnt] = d; cvv[cnt] = vcode; cnt++; }
                        }
                    }
                }
            }
            __syncthreads();
        }
    }

    if (tid < FM) {
        int n = m0 + tid;
        int jj = 0;
        for (int i2 = 0; i2 < cnt; i2++)
            if (cdv[i2] <= bthr) { cvv[jj] = cvv[i2]; jj++; }
        g_ncand[n] = bad ? -1 : jj;
        for (int i2 = 0; i2 < jj; i2++) g_cand[(size_t)n * CAND_CAP + i2] = cvv[i2];
    }
    #undef LOADB
    #undef STSB
}

// ============================================================
// Kernel 3: exact rescore of candidates (identical fp32 chain
// to the proven-exact dist kernel). One warp per row;
// first-index min semantics.
// ============================================================
__global__ __launch_bounds__(256) void rescore_kernel(
    const float* __restrict__ emb, float* __restrict__ out_tok)
{
    int n    = blockIdx.x * 8 + (threadIdx.x >> 5);
    int lane = threadIdx.x & 31;
    int nc   = g_ncand[n];

    if (nc == 1) {
        if (lane == 0) {
            int v = g_cand[(size_t)n * CAND_CAP];
            g_tok[n] = v;
            out_tok[n] = (float)v;
        }
        return;
    }

    const float* zr = g_zp + (size_t)n * E_DIM;
    float bdv = 3.4e38f;
    int   bvi = 0x7fffffff;

    if (nc >= 0) {
        int v = (lane < nc) ? g_cand[(size_t)n * CAND_CAP + lane] : -1;
        if (v >= 0) {
            const float* er = emb + (size_t)v * E_DIM;
            float dot = 0.f;
            #pragma unroll 8
            for (int k = 0; k < E_DIM; k += 4) {
                float4 a = *(const float4*)(zr + k);
                float4 bb = *(const float4*)(er + k);
                dot = fmaf(a.x, bb.x, dot);
                dot = fmaf(a.y, bb.y, dot);
                dot = fmaf(a.z, bb.z, dot);
                dot = fmaf(a.w, bb.w, dot);
            }
            bdv = fmaf(-2.0f, dot, g_C[n] + g_e2[v]);
            bvi = v;
        }
    } else {
        // overflow fallback: exact full scan of the row
        for (int v = lane; v < V_SIZE; v += 32) {
            const float* er = emb + (size_t)v * E_DIM;
            float dot = 0.f;
            #pragma unroll 8
            for (int k = 0; k < E_DIM; k += 4) {
                float4 a = *(const float4*)(zr + k);
                float4 bb = *(const float4*)(er + k);
                dot = fmaf(a.x, bb.x, dot);
                dot = fmaf(a.y, bb.y, dot);
                dot = fmaf(a.z, bb.z, dot);
                dot = fmaf(a.w, bb.w, dot);
            }
            float d = fmaf(-2.0f, dot, g_C[n] + g_e2[v]);
            if (d < bdv) { bdv = d; bvi = v; }
        }
    }

    #pragma unroll
    for (int off = 16; off > 0; off >>= 1) {
        float od = __shfl_xor_sync(0xffffffffu, bdv, off);
        int   ov = __shfl_xor_sync(0xffffffffu, bvi, off);
        if (od < bdv || (od == bdv && ov < bvi)) { bdv = od; bvi = ov; }
    }
    if (lane == 0) {
        g_tok[n] = bvi;
        out_tok[n] = (float)bvi;
    }
}

// ============================================================
// Kernel 4: P = emb @ post_W + post_b   [2048, 64]
// ============================================================
#define BM 64
#define BK 32

__global__ __launch_bounds__(256) void pmat_kernel(
    const float* __restrict__ emb, const float* __restrict__ W,
    const float* __restrict__ b)
{
    __shared__ float As2[BK][BM + 4];
    __shared__ float Bs2[BK][64 + 4];

    int m0  = blockIdx.x * BM;
    int tid = threadIdx.x;
    int tx  = tid & 15;
    int ty  = tid >> 4;

    float acc[4][4];
    #pragma unroll
    for (int i = 0; i < 4; i++)
        #pragma unroll
        for (int jj = 0; jj < 4; jj++) acc[i][jj] = 0.f;

    for (int k0 = 0; k0 < E_DIM; k0 += BK) {
        #pragma unroll
        for (int i = 0; i < 8; i++) {
            int idx = tid + 256 * i;
            int m = idx >> 5, kk = idx & 31;
            As2[kk][m] = emb[(size_t)(m0 + m) * E_DIM + k0 + kk];
        }
        #pragma unroll
        for (int i = 0; i < 8; i++) {
            int idx = tid + 256 * i;
            int kk = idx >> 6, jj = idx & 63;
            Bs2[kk][jj] = W[(size_t)(k0 + kk) * 64 + jj];
        }
        __syncthreads();
        #pragma unroll
        for (int kk = 0; kk < BK; kk++) {
            float a[4], bb[4];
            *(float4*)a  = *(const float4*)&As2[kk][ty * 4];
            *(float4*)bb = *(const float4*)&Bs2[kk][tx * 4];
            #pragma unroll
            for (int i = 0; i < 4; i++)
                #pragma unroll
                for (int jj = 0; jj < 4; jj++)
                    acc[i][jj] = fmaf(a[i], bb[jj], acc[i][jj]);
        }
        __syncthreads();
    }

    float bb0 = b[tx * 4 + 0], bb1 = b[tx * 4 + 1],
          bb2 = b[tx * 4 + 2], bb3 = b[tx * 4 + 3];
    #pragma unroll
    for (int i = 0; i < 4; i++) {
        int n = m0 + ty * 4 + i;
        float4 r;
        r.x = acc[i][0] + bb0;
        r.y = acc[i][1] + bb1;
        r.z = acc[i][2] + bb2;
        r.w = acc[i][3] + bb3;
        *(float4*)&g_P[(size_t)n * 64 + tx * 4] = r;
    }
}

// ============================================================
// Kernel 5: z_q[n] = P[tok[n]]  (pure gather)
// ============================================================
__global__ __launch_bounds__(256) void gather_kernel(float* __restrict__ out)
{
    int idx = blockIdx.x * 256 + threadIdx.x;
    int n = idx >> 4;
    int c = idx & 15;
    int tok = g_tok[n];
    float4 v = *(const float4*)&g_P[(size_t)tok * 64 + c * 4];
    *(float4*)&out[(size_t)n * 64 + c * 4] = v;
}

// ============================================================
extern "C" void kernel_launch(void* const* d_in, const int* in_sizes, int n_in,
                              void* d_out, int out_size)
{
    const float* z      = (const float*)d_in[0];   // [N, 64]
    const float* emb_W  = (const float*)d_in[1];   // [2048, 512]
    const float* pre_W  = (const float*)d_in[2];   // [64, 512]
    const float* pre_b  = (const float*)d_in[3];   // [512]
    const float* post_W = (const float*)d_in[4];   // [512, 64]
    const float* post_b = (const float*)d_in[5];   // [64]

    float* out = (float*)d_out;
    float* out_tok = out;                 // [N] tokens (as float)
    float* out_zq  = out + N_TOK;         // [N, 64]

    cudaFuncSetAttribute(filter_kernel,
                         cudaFuncAttributeMaxDynamicSharedMemorySize, FIL_SMEM);

    e2_kernel    <<<V_SIZE, 128>>>(emb_W);
    pre_kernel   <<<N_TOK, 128>>>(z, pre_W, pre_b);
    pmat_kernel  <<<V_SIZE / BM, 256>>>(emb_W, post_W, post_b);
    filter_kernel<<<N_TOK / FM, 256, FIL_SMEM>>>();
    rescore_kernel<<<N_TOK / 8, 256>>>(emb_W, out_tok);
    gather_kernel<<<(N_TOK * 16) / 256, 256>>>(out_zq);
}